// round 15
// baseline (speedup 1.0000x reference)
#include <cuda_runtime.h>
#include <cstdint>

#define B_ 8
#define T_ 50
#define P_ 1024
#define S_ 128
#define O_ 32
#define H_ 128
#define R_ (B_*P_)
#define NG_ 512
#define KC_ 256          // fused K for BOTH layers (obs hoisted out of layer 1)

#define TINY_ 1.17549435e-38f
#define LO_   -0.99999994039535522461f
#define SQRT2_ 1.41421356237309504880f

// ---------------- device scratch (static, no runtime allocation) -------------
__device__ float d_h1[R_*S_], d_c1[R_*S_], d_h2[R_*S_], d_c2[R_*S_];
__device__ float d_c1g[R_*S_], d_c2g[R_*S_];
__device__ float d_A1[R_*KC_];   // [noise(128) | h1_gathered(128)]
__device__ float d_A2[R_*KC_];   // [h1_new(128) | h2_gathered(128)]
__device__ float d_Am[R_*H_];    // h2_new (obs part hoisted)
__device__ float d_w[R_];
__device__ float d_obsZ[B_*NG_]; // obs @ W1[128:160]  (gate-major cols)
__device__ float d_mObs[B_*H_];  // obs @ Wm1[0:32]
// tf32-split, mma-fragment-interleaved fused weights
__device__ float d_Wc1h[KC_*NG_], d_Wc1l[KC_*NG_];
__device__ float d_Wc2h[KC_*NG_], d_Wc2l[KC_*NG_];

// ---------------- cp.async helpers -------------------------------------------
__device__ __forceinline__ uint32_t smem_u32(const void* p) {
    return (uint32_t)__cvta_generic_to_shared(p);
}
#define CP_ASYNC16(dst_u32, src_ptr) \
    asm volatile("cp.async.cg.shared.global [%0], [%1], 16;" :: "r"(dst_u32), "l"(src_ptr))
#define CP_COMMIT()  asm volatile("cp.async.commit_group;")
#define CP_WAIT0()   asm volatile("cp.async.wait_group 0;")

// tf32 helpers
__device__ __forceinline__ uint32_t tf32_bits(float a) {
    uint32_t r;
    asm("cvt.rna.tf32.f32 %0, %1;" : "=r"(r) : "f"(a));
    return r;
}

#define MMA_TF32(d, a, b) \
    asm volatile("mma.sync.aligned.m16n8k8.row.col.f32.tf32.tf32.f32 " \
        "{%0,%1,%2,%3}, {%4,%5,%6,%7}, {%8,%9}, {%0,%1,%2,%3};" \
        : "+f"((d)[0]), "+f"((d)[1]), "+f"((d)[2]), "+f"((d)[3]) \
        : "r"((a)[0]), "r"((a)[1]), "r"((a)[2]), "r"((a)[3]), \
          "r"((b)[0]), "r"((b)[1]))

// ---------------- threefry2x32 (JAX schedule) --------------------------------
__device__ __forceinline__ uint32_t rb32(uint32_t k0, uint32_t k1, uint32_t ctr) {
    uint32_t ks2 = k0 ^ k1 ^ 0x1BD11BDAu;
    uint32_t x0 = 0u + k0, x1 = ctr + k1;
#define TFR_(r) { x0 += x1; x1 = __funnelshift_l(x1, x1, (r)); x1 ^= x0; }
    TFR_(13) TFR_(15) TFR_(26) TFR_(6)
    x0 += k1;  x1 += ks2 + 1u;
    TFR_(17) TFR_(29) TFR_(16) TFR_(24)
    x0 += ks2; x1 += k0 + 2u;
    TFR_(13) TFR_(15) TFR_(26) TFR_(6)
    x0 += k0;  x1 += k1 + 3u;
    TFR_(17) TFR_(29) TFR_(16) TFR_(24)
    x0 += k1;  x1 += ks2 + 4u;
    TFR_(13) TFR_(15) TFR_(26) TFR_(6)
    x0 += ks2; x1 += k0 + 5u;
#undef TFR_
    return x0 ^ x1;
}

// ---------------- XLA-matched math -------------------------------------------
__device__ __forceinline__ float tanh_x(float x) {
    float ax = fabsf(x);
    float xc = fminf(fmaxf(x, -7.90531110763549805f), 7.90531110763549805f);
    float x2 = __fmul_rn(xc, xc);
    float p = -2.76076847742355e-16f;
    p = fmaf(p, x2,  2.00018790482477e-13f);
    p = fmaf(p, x2, -8.60467152213735e-11f);
    p = fmaf(p, x2,  5.12229709037114e-08f);
    p = fmaf(p, x2,  1.48572235717979e-05f);
    p = fmaf(p, x2,  6.37261928875436e-04f);
    p = fmaf(p, x2,  4.89352455891786e-03f);
    float num = __fmul_rn(xc, p);
    float q = 1.19825839466702e-06f;
    q = fmaf(q, x2, 1.18534705686654e-04f);
    q = fmaf(q, x2, 2.26843463243900e-03f);
    q = fmaf(q, x2, 4.89352518554385e-03f);
    return (ax < 0.0004f) ? x : __fdiv_rn(num, q);
}

__device__ __forceinline__ float sig_x(float x) {
    return __fadd_rn(__fmul_rn(0.5f, tanh_x(__fmul_rn(0.5f, x))), 0.5f);
}

__device__ __forceinline__ float erfinv_x(float x) {
    float t = __fmul_rn(x, x);
    float w = -log1pf(-t);
    float p;
    if (w < 5.0f) {
        w = __fadd_rn(w, -2.5f);
        p = 2.81022636e-08f;
        p = __fadd_rn(__fmul_rn(p, w),  3.43273939e-07f);
        p = __fadd_rn(__fmul_rn(p, w), -3.5233877e-06f);
        p = __fadd_rn(__fmul_rn(p, w), -4.39150654e-06f);
        p = __fadd_rn(__fmul_rn(p, w),  0.00021858087f);
        p = __fadd_rn(__fmul_rn(p, w), -0.00125372503f);
        p = __fadd_rn(__fmul_rn(p, w), -0.00417768164f);
        p = __fadd_rn(__fmul_rn(p, w),  0.246640727f);
        p = __fadd_rn(__fmul_rn(p, w),  1.50140941f);
    } else {
        w = __fadd_rn(__fsqrt_rn(w), -3.0f);
        p = -0.000200214257f;
        p = __fadd_rn(__fmul_rn(p, w),  0.000100950558f);
        p = __fadd_rn(__fmul_rn(p, w),  0.00134934322f);
        p = __fadd_rn(__fmul_rn(p, w), -0.00367342844f);
        p = __fadd_rn(__fmul_rn(p, w),  0.00573950773f);
        p = __fadd_rn(__fmul_rn(p, w), -0.0076224613f);
        p = __fadd_rn(__fmul_rn(p, w),  0.00943887047f);
        p = __fadd_rn(__fmul_rn(p, w),  1.00167406f);
        p = __fadd_rn(__fmul_rn(p, w),  2.83297682f);
    }
    return __fmul_rn(p, x);
}

// ---------------- small kernels ----------------------------------------------
__global__ void init_state_kernel() {
    int e = blockIdx.x * 256 + threadIdx.x;
    if (e < R_*S_) { d_h1[e]=0.f; d_c1[e]=0.f; d_h2[e]=0.f; d_c2[e]=0.f; }
    if (e < R_)    { d_w[e] = 1.0f/1024.0f; }
}

// per-step hoisted obs contributions: obsZ = obs@W1[128:160], mObs = obs@Wm1[0:32]
__global__ void obsprep_kernel(const float* __restrict__ obs,
                               const float* __restrict__ W1,
                               const float* __restrict__ Wm1, int t) {
    int b = blockIdx.x;
    int c = threadIdx.x;          // 0..511
    __shared__ float ob[O_];
    if (c < O_) ob[c] = obs[((size_t)b*T_ + t)*O_ + c];
    __syncthreads();
    float acc = 0.f;
    #pragma unroll 8
    for (int o = 0; o < O_; o++)
        acc = fmaf(ob[o], W1[(size_t)(128 + o)*NG_ + c], acc);
    d_obsZ[b*NG_ + c] = acc;
    if (c < H_) {
        float a2 = 0.f;
        #pragma unroll 8
        for (int o = 0; o < O_; o++)
            a2 = fmaf(ob[o], Wm1[(size_t)o*H_ + c], a2);
        d_mObs[b*H_ + c] = a2;
    }
}

// fragment interleave: global col C -> source gate-major col
__device__ __forceinline__ int src_col_map(int C) {
    int c = C & 127;
    int wn = c >> 6, r = c & 63;
    int u = r >> 3, j = (r >> 1) & 3, v = r & 1;
    int g = 2*(u >> 2) + v;
    int s = ((C & ~127) >> 2) + 16*wn + 4*(u & 3) + j;
    return g*128 + s;
}

__global__ void build_wc_kernel(const float* __restrict__ W1, const float* __restrict__ U1,
                                const float* __restrict__ W2, const float* __restrict__ U2) {
    int i = blockIdx.x * 256 + threadIdx.x;
    if (i < KC_*NG_) {
        int k = i / NG_, C = i % NG_;
        int src = src_col_map(C);
        float wv1 = (k < 128) ? W1[k*NG_ + src] : U1[(k-128)*NG_ + src];
        uint32_t hb = tf32_bits(wv1);
        float hf = __uint_as_float(hb);
        d_Wc1h[i] = hf;
        d_Wc1l[i] = __uint_as_float(tf32_bits(__fadd_rn(wv1, -hf)));
        float wv2 = (k < 128) ? W2[k*NG_ + src] : U2[(k-128)*NG_ + src];
        uint32_t hb2 = tf32_bits(wv2);
        float hf2 = __uint_as_float(hb2);
        d_Wc2h[i] = hf2;
        d_Wc2l[i] = __uint_as_float(tf32_bits(__fadd_rn(wv2, -hf2)));
    }
}

// fused: categorical resample (warp 0, identical op order) + state gather + noise
__global__ void __launch_bounds__(128) gather_kernel(uint32_t a0, uint32_t a1,
                                                     uint32_t n0, uint32_t n1, int doRes) {
    __shared__ int sidx;
    int r = blockIdx.x;
    int tid = threadIdx.x;

    if (doRes) {
        if (tid < 32) {
            int lane = tid;
            const float* wb = d_w + (r & ~1023);
            uint32_t base = ((uint32_t)r) << 10;
            float best = -__int_as_float(0x7f800000);
            int bestj = 0;
            for (int it = 0; it < 32; it++) {
                int j = it*32 + lane;
                uint32_t bits = rb32(a0, a1, base + (uint32_t)j);
                float u01 = __uint_as_float((bits >> 9) | 0x3f800000u) - 1.0f;
                float u = fmaxf(TINY_, __fadd_rn(u01, TINY_));
                float l1 = logf(u);
                float g  = -logf(-l1);
                float v  = __fadd_rn(g, __ldg(&wb[j]));
                if (v > best) { best = v; bestj = j; }
            }
            for (int off = 16; off; off >>= 1) {
                float ov = __shfl_xor_sync(0xffffffffu, best, off);
                int   oj = __shfl_xor_sync(0xffffffffu, bestj, off);
                if (ov > best || (ov == best && oj < bestj)) { best = ov; bestj = oj; }
            }
            if (lane == 0) sidx = bestj;
        }
    } else if (tid == 0) {
        sidx = 0;
    }
    __syncthreads();

    int s = tid;
    int src = (r & ~1023) + sidx;
    uint32_t bits = rb32(n0, n1, (uint32_t)(r*S_ + s));
    float u01 = __uint_as_float((bits >> 9) | 0x3f800000u) - 1.0f;
    float u = fmaxf(LO_, __fadd_rn(__fmul_rn(u01, 2.0f), LO_));
    float nz = __fmul_rn((float)SQRT2_, erfinv_x(u));
    size_t r1 = (size_t)r * KC_;
    d_A1[r1 + s]        = nz;
    d_A1[r1 + 128 + s]  = d_h1[(size_t)src*S_ + s];
    d_c1g[(size_t)r*S_ + s] = d_c1[(size_t)src*S_ + s];
    d_A2[(size_t)r*KC_ + 128 + s] = d_h2[(size_t)src*S_ + s];
    d_c2g[(size_t)r*S_ + s] = d_c2[(size_t)src*S_ + s];
}

// ---------------- 3xTF32 tensor-core GEMM + fused LSTM epilogue --------------
// CH=16, PAD 136 layout. TERM-MAJOR MMA issue: for each k-oct, issue term 1
// (ah*bl) for all 16 accumulators, then term 2 (al*bh), then term 3 (ah*bh).
// Per-accumulator arrival order stays t1,t2,t3 -> bit-identical results; the
// 16-issue spacing between dependent MMAs hides tensor-pipe latency.
#define BM_ 128
#define BN_ 128
#define CH_ 16
#define PAD_ 136
#define NCHF_ (CH_*PAD_)                 // floats per (buf,array) = 2176
#define GSMEM_ (4*2*NCHF_*4)             // 69632 B

template<int LAYER>
__global__ void __launch_bounds__(256, 2) gemm_lstm_kernel(const float* __restrict__ bias,
                                                           float* __restrict__ out, int t) {
    extern __shared__ float sm[];
    float* Ah = sm;                      // [buf*NCHF_ + k*PAD_ + row]
    float* Al = Ah + 2*NCHF_;
    float* Bh = Al + 2*NCHF_;
    float* Bl = Bh + 2*NCHF_;

    const int K = KC_;
    const float* __restrict__ A   = (LAYER == 1) ? d_A1 : d_A2;
    const float* __restrict__ Whi = (LAYER == 1) ? d_Wc1h : d_Wc2h;
    const float* __restrict__ Wlo = (LAYER == 1) ? d_Wc1l : d_Wc2l;
    const float* __restrict__ Cg  = (LAYER == 1) ? d_c1g : d_c2g;

    int tid = threadIdx.x;
    int warp = tid >> 5, lane = tid & 31;
    int wm = warp >> 1, wn = warp & 1;
    int q = lane >> 2, j = lane & 3;
    int rowBase = blockIdx.y * BM_;
    int colBase = blockIdx.x * BN_;
    const int NT = K / CH_;              // 16

    int ldRow = tid & 127, ldKq = tid >> 7;      // A: 2 threads/row
    int bKr = tid >> 5, bCc = (tid & 31) * 4;    // B: rows bKr, bKr+8
    const float* aRow = A + (size_t)(rowBase + ldRow) * K;

    float acc[2][8][4];
    #pragma unroll
    for (int a = 0; a < 2; a++)
        #pragma unroll
        for (int u = 0; u < 8; u++)
            #pragma unroll
            for (int x = 0; x < 4; x++) acc[a][u][x] = 0.f;

    auto stage_a = [&](int buf, float4 av, int oct) {
        #pragma unroll
        for (int i = 0; i < 4; i++) {
            float a = (&av.x)[i];
            uint32_t hb = tf32_bits(a);
            float hf = __uint_as_float(hb);
            uint32_t lb = tf32_bits(__fadd_rn(a, -hf));
            int kk = oct*8 + ldKq*4 + i;
            Ah[buf*NCHF_ + kk*PAD_ + ldRow] = hf;
            Al[buf*NCHF_ + kk*PAD_ + ldRow] = __uint_as_float(lb);
        }
    };
    auto cp_b = [&](int k0, int buf) {
        #pragma unroll
        for (int rr = 0; rr < 2; rr++) {
            int row = bKr + rr*8;
            CP_ASYNC16(smem_u32(&Bh[buf*NCHF_ + row*PAD_ + bCc]),
                       &Whi[(size_t)(k0 + row)*NG_ + colBase + bCc]);
            CP_ASYNC16(smem_u32(&Bl[buf*NCHF_ + row*PAD_ + bCc]),
                       &Wlo[(size_t)(k0 + row)*NG_ + colBase + bCc]);
        }
        CP_COMMIT();
    };

    // prologue: chunk 0
    float4 av0 = *reinterpret_cast<const float4*>(aRow + ldKq*4);
    float4 av1 = *reinterpret_cast<const float4*>(aRow + 8 + ldKq*4);
    cp_b(0, 0);
    stage_a(0, av0, 0);
    stage_a(0, av1, 1);
    CP_WAIT0();
    __syncthreads();

    for (int kt = 0; kt < NT; kt++) {
        int buf = kt & 1, nb = buf ^ 1;
        if (kt + 1 < NT) {
            int k0 = (kt + 1) * CH_;
            av0 = *reinterpret_cast<const float4*>(aRow + k0 + ldKq*4);
            av1 = *reinterpret_cast<const float4*>(aRow + k0 + 8 + ldKq*4);
            cp_b(k0, nb);
        }

        #pragma unroll
        for (int oct = 0; oct < 2; oct++) {
            int kb = oct*8;
            const float* AhB = Ah + buf*NCHF_;
            const float* AlB = Al + buf*NCHF_;
            const float* BhB = Bh + buf*NCHF_;
            const float* BlB = Bl + buf*NCHF_;
            uint32_t ah[2][4], al[2][4];
            #pragma unroll
            for (int mt = 0; mt < 2; mt++) {
                int r0 = wm*32 + mt*16 + q;
                ah[mt][0] = __float_as_uint(AhB[(kb+j)*PAD_ + r0]);
                ah[mt][1] = __float_as_uint(AhB[(kb+j)*PAD_ + r0+8]);
                ah[mt][2] = __float_as_uint(AhB[(kb+j+4)*PAD_ + r0]);
                ah[mt][3] = __float_as_uint(AhB[(kb+j+4)*PAD_ + r0+8]);
                al[mt][0] = __float_as_uint(AlB[(kb+j)*PAD_ + r0]);
                al[mt][1] = __float_as_uint(AlB[(kb+j)*PAD_ + r0+8]);
                al[mt][2] = __float_as_uint(AlB[(kb+j+4)*PAD_ + r0]);
                al[mt][3] = __float_as_uint(AlB[(kb+j+4)*PAD_ + r0+8]);
            }
            // term 1: ah x bl  (all 16 accumulators)
            #pragma unroll
            for (int u = 0; u < 8; u++) {
                int c0 = wn*64 + u*8 + q;
                uint32_t bl[2];
                bl[0] = __float_as_uint(BlB[(kb+j)*PAD_ + c0]);
                bl[1] = __float_as_uint(BlB[(kb+j+4)*PAD_ + c0]);
                MMA_TF32(acc[0][u], ah[0], bl);
                MMA_TF32(acc[1][u], ah[1], bl);
            }
            // term 2: al x bh
            #pragma unroll
            for (int u = 0; u < 8; u++) {
                int c0 = wn*64 + u*8 + q;
                uint32_t bh[2];
                bh[0] = __float_as_uint(BhB[(kb+j)*PAD_ + c0]);
                bh[1] = __float_as_uint(BhB[(kb+j+4)*PAD_ + c0]);
                MMA_TF32(acc[0][u], al[0], bh);
                MMA_TF32(acc[1][u], al[1], bh);
            }
            // term 3: ah x bh
            #pragma unroll
            for (int u = 0; u < 8; u++) {
                int c0 = wn*64 + u*8 + q;
                uint32_t bh[2];
                bh[0] = __float_as_uint(BhB[(kb+j)*PAD_ + c0]);
                bh[1] = __float_as_uint(BhB[(kb+j+4)*PAD_ + c0]);
                MMA_TF32(acc[0][u], ah[0], bh);
                MMA_TF32(acc[1][u], ah[1], bh);
            }
        }

        if (kt + 1 < NT) {
            stage_a(nb, av0, 0);
            stage_a(nb, av1, 1);
            CP_WAIT0();
            __syncthreads();
        }
    }

    // ---------------- LSTM epilogue --------------------------------------
    int sBase = (colBase >> 2) + 16*wn;
    const float* oZ = (LAYER == 1) ? (d_obsZ + (size_t)(rowBase >> 10)*NG_) : nullptr;
    #pragma unroll
    for (int mt = 0; mt < 2; mt++) {
        #pragma unroll
        for (int half = 0; half < 2; half++) {
            int row = rowBase + wm*32 + mt*16 + q + half*8;
            #pragma unroll
            for (int ul = 0; ul < 4; ul++) {
                int s = sBase + 4*ul + j;
                float zi, zf, zg, zo;
                if (LAYER == 1) {
                    zi = __fadd_rn(__fadd_rn(acc[mt][ul  ][half*2+0], oZ[s]),       bias[s]);
                    zf = __fadd_rn(__fadd_rn(acc[mt][ul  ][half*2+1], oZ[128 + s]), bias[128 + s]);
                    zg = __fadd_rn(__fadd_rn(acc[mt][ul+4][half*2+0], oZ[256 + s]), bias[256 + s]);
                    zo = __fadd_rn(__fadd_rn(acc[mt][ul+4][half*2+1], oZ[384 + s]), bias[384 + s]);
                } else {
                    zi = __fadd_rn(acc[mt][ul  ][half*2+0], bias[s]);
                    zf = __fadd_rn(acc[mt][ul  ][half*2+1], bias[128 + s]);
                    zg = __fadd_rn(acc[mt][ul+4][half*2+0], bias[256 + s]);
                    zo = __fadd_rn(acc[mt][ul+4][half*2+1], bias[384 + s]);
                }
                float c  = Cg[(size_t)row*S_ + s];
                float cn = __fadd_rn(__fmul_rn(sig_x(zf), c), __fmul_rn(sig_x(zi), tanh_x(zg)));
                float hn = __fmul_rn(sig_x(zo), tanh_x(cn));
                if (LAYER == 1) {
                    d_h1[(size_t)row*S_ + s] = hn;
                    d_c1[(size_t)row*S_ + s] = cn;
                    d_A2[(size_t)row*KC_ + s] = hn;
                } else {
                    d_h2[(size_t)row*S_ + s] = hn;
                    d_c2[(size_t)row*S_ + s] = cn;
                    d_Am[(size_t)row*H_ + s] = hn;
                    int b = row >> 10, p = row & 1023;
                    out[(((size_t)b*T_ + t)*P_ + p)*129 + s] = hn;
                }
            }
        }
    }
}

// measurement MLP: w = relu(h2 @ Wm1[32:] + mObs + bm1) @ Wm2 + bm2
#define MEAS_ROWS 64
#define MEAS_SMEM ((H_*H_ + H_ + MEAS_ROWS*H_) * 4)
__global__ void __launch_bounds__(256) meas_kernel(const float* __restrict__ Wm1,
                                                   const float* __restrict__ bm1,
                                                   const float* __restrict__ Wm2,
                                                   const float* __restrict__ bm2,
                                                   float* __restrict__ out, int t) {
    extern __shared__ float sm[];
    float* sW  = sm;                 // Wm1 rows 32..159: 128x128
    float* sW2 = sW + H_*H_;
    float* sR  = sW2 + H_;
    int tid = threadIdx.x;
    int rowBase = blockIdx.x * MEAS_ROWS;
    int bb = rowBase >> 10;
    for (int i = tid; i < H_*H_; i += 256) sW[i] = Wm1[O_*H_ + i];
    if (tid < H_) sW2[tid] = Wm2[tid];
    for (int i = tid; i < MEAS_ROWS*H_; i += 256) sR[i] = d_Am[(size_t)rowBase*H_ + i];
    __syncthreads();
    int warp = tid >> 5, lane = tid & 31;
    float b2v = bm2[0];
    const float* mOb = d_mObs + (size_t)bb*H_;
    for (int rl = warp; rl < MEAS_ROWS; rl += 8) {
        const float* x = sR + rl*H_;
        float d0 = 0.f, d1 = 0.f, d2 = 0.f, d3 = 0.f;
        #pragma unroll 4
        for (int k = 0; k < H_; k++) {
            float xv = x[k];
            float4 wv = *reinterpret_cast<const float4*>(&sW[k*H_ + lane*4]);
            d0 = fmaf(xv, wv.x, d0); d1 = fmaf(xv, wv.y, d1);
            d2 = fmaf(xv, wv.z, d2); d3 = fmaf(xv, wv.w, d3);
        }
        int c0 = lane*4;
        d0 = fmaxf(__fadd_rn(__fadd_rn(d0, mOb[c0+0]), bm1[c0+0]), 0.f);
        d1 = fmaxf(__fadd_rn(__fadd_rn(d1, mOb[c0+1]), bm1[c0+1]), 0.f);
        d2 = fmaxf(__fadd_rn(__fadd_rn(d2, mOb[c0+2]), bm1[c0+2]), 0.f);
        d3 = fmaxf(__fadd_rn(__fadd_rn(d3, mOb[c0+3]), bm1[c0+3]), 0.f);
        float acc = fmaf(d3, sW2[c0+3], fmaf(d2, sW2[c0+2], fmaf(d1, sW2[c0+1], __fmul_rn(d0, sW2[c0+0]))));
        for (int off = 16; off; off >>= 1) acc += __shfl_xor_sync(0xffffffffu, acc, off);
        if (lane == 0) {
            float wn = __fadd_rn(acc, b2v);
            int r = rowBase + rl;
            d_w[r] = wn;
            int b = r >> 10, p = r & 1023;
            out[(((size_t)b*T_ + t)*P_ + p)*129 + 128] = wn;
        }
    }
}

// ---------------- host side --------------------------------------------------
static inline uint32_t rotl32_h(uint32_t x, int r) { return (x << r) | (x >> (32 - r)); }
static void tf_host(uint32_t k0, uint32_t k1, uint32_t x0, uint32_t x1,
                    uint32_t* o0, uint32_t* o1) {
    uint32_t ks2 = k0 ^ k1 ^ 0x1BD11BDAu;
    x0 += k0; x1 += k1;
#define HR_(r) { x0 += x1; x1 = rotl32_h(x1, (r)); x1 ^= x0; }
    HR_(13) HR_(15) HR_(26) HR_(6)
    x0 += k1;  x1 += ks2 + 1u;
    HR_(17) HR_(29) HR_(16) HR_(24)
    x0 += ks2; x1 += k0 + 2u;
    HR_(13) HR_(15) HR_(26) HR_(6)
    x0 += k0;  x1 += k1 + 3u;
    HR_(17) HR_(29) HR_(16) HR_(24)
    x0 += k1;  x1 += ks2 + 4u;
    HR_(13) HR_(15) HR_(26) HR_(6)
    x0 += ks2; x1 += k0 + 5u;
#undef HR_
    *o0 = x0; *o1 = x1;
}

extern "C" void kernel_launch(void* const* d_in, const int* in_sizes, int n_in,
                              void* d_out, int out_size) {
    (void)in_sizes; (void)n_in; (void)out_size;
    const float* obs = (const float*)d_in[0];
    const float* W1  = (const float*)d_in[1];
    const float* U1  = (const float*)d_in[2];
    const float* b1  = (const float*)d_in[3];
    const float* W2  = (const float*)d_in[4];
    const float* U2  = (const float*)d_in[5];
    const float* b2  = (const float*)d_in[6];
    const float* Wm1 = (const float*)d_in[7];
    const float* bm1 = (const float*)d_in[8];
    const float* Wm2 = (const float*)d_in[9];
    const float* bm2 = (const float*)d_in[10];
    float* out = (float*)d_out;

    cudaFuncSetAttribute(meas_kernel, cudaFuncAttributeMaxDynamicSharedMemorySize, MEAS_SMEM);
    cudaFuncSetAttribute(gemm_lstm_kernel<1>, cudaFuncAttributeMaxDynamicSharedMemorySize, GSMEM_);
    cudaFuncSetAttribute(gemm_lstm_kernel<2>, cudaFuncAttributeMaxDynamicSharedMemorySize, GSMEM_);

    init_state_kernel<<<(R_*S_ + 255)/256, 256>>>();
    build_wc_kernel<<<(KC_*NG_ + 255)/256, 256>>>(W1, U1, W2, U2);

    uint32_t root0 = 0u, root1 = 42u;
    for (int t = 0; t < T_; t++) {
        uint32_t kt0, kt1, a0, a1, n0, n1;
        tf_host(root0, root1, 0u, (uint32_t)t, &kt0, &kt1);
        tf_host(kt0, kt1, 0u, 0u, &a0, &a1);
        tf_host(kt0, kt1, 0u, 1u, &n0, &n1);

        obsprep_kernel<<<B_, NG_>>>(obs, W1, Wm1, t);
        // t=0: all LSTM states are zero -> categorical resample is dead code.
        gather_kernel<<<R_, 128>>>(a0, a1, n0, n1, t > 0 ? 1 : 0);
        gemm_lstm_kernel<1><<<dim3(NG_/BN_, R_/BM_), 256, GSMEM_>>>(b1, nullptr, t);
        gemm_lstm_kernel<2><<<dim3(NG_/BN_, R_/BM_), 256, GSMEM_>>>(b2, out, t);
        meas_kernel<<<R_/MEAS_ROWS, 256, MEAS_SMEM>>>(Wm1, bm1, Wm2, bm2, out, t);
    }
}

// round 16
// speedup vs baseline: 1.2298x; 1.2298x over previous
#include <cuda_runtime.h>
#include <cuda_fp16.h>
#include <cstdint>

#define B_ 8
#define T_ 50
#define P_ 1024
#define S_ 128
#define O_ 32
#define H_ 128
#define R_ (B_*P_)
#define NG_ 512
#define KC_ 256          // fused K for BOTH layers (obs hoisted out of layer 1)

#define TINY_ 1.17549435e-38f
#define LO_   -0.99999994039535522461f
#define SQRT2_ 1.41421356237309504880f

// ---------------- device scratch (static, no runtime allocation) -------------
__device__ float d_h1[R_*S_], d_c1[R_*S_], d_h2[R_*S_], d_c2[R_*S_];
__device__ float d_c1g[R_*S_], d_c2g[R_*S_];
__device__ float d_A1[R_*KC_];   // [noise(128) | h1_gathered(128)]
__device__ float d_A2[R_*KC_];   // [h1_new(128) | h2_gathered(128)]
__device__ float d_Am[R_*H_];    // h2_new (obs part hoisted)
__device__ float d_w[R_];
__device__ float d_obsZ[B_*NG_]; // obs @ W1[128:160]  (gate-major cols)
__device__ float d_mObs[B_*H_];  // obs @ Wm1[0:32]
// fp16-split, half2-packed fused weights: [k/2][col] half2 (k-pair major)
__device__ __half2 d_Wc1h[(KC_/2)*NG_], d_Wc1l[(KC_/2)*NG_];
__device__ __half2 d_Wc2h[(KC_/2)*NG_], d_Wc2l[(KC_/2)*NG_];

// ---------------- cp.async helpers -------------------------------------------
__device__ __forceinline__ uint32_t smem_u32(const void* p) {
    return (uint32_t)__cvta_generic_to_shared(p);
}
#define CP_ASYNC16(dst_u32, src_ptr) \
    asm volatile("cp.async.cg.shared.global [%0], [%1], 16;" :: "r"(dst_u32), "l"(src_ptr))
#define CP_COMMIT()  asm volatile("cp.async.commit_group;")
#define CP_WAIT0()   asm volatile("cp.async.wait_group 0;")

// fp16 m16n8k16 MMA, fp32 accumulate
#define MMA_F16(d, a, b) \
    asm volatile("mma.sync.aligned.m16n8k16.row.col.f32.f16.f16.f32 " \
        "{%0,%1,%2,%3}, {%4,%5,%6,%7}, {%8,%9}, {%0,%1,%2,%3};" \
        : "+f"((d)[0]), "+f"((d)[1]), "+f"((d)[2]), "+f"((d)[3]) \
        : "r"((a)[0]), "r"((a)[1]), "r"((a)[2]), "r"((a)[3]), \
          "r"((b)[0]), "r"((b)[1]))

// ---------------- threefry2x32 (JAX schedule) --------------------------------
__device__ __forceinline__ uint32_t rb32(uint32_t k0, uint32_t k1, uint32_t ctr) {
    uint32_t ks2 = k0 ^ k1 ^ 0x1BD11BDAu;
    uint32_t x0 = 0u + k0, x1 = ctr + k1;
#define TFR_(r) { x0 += x1; x1 = __funnelshift_l(x1, x1, (r)); x1 ^= x0; }
    TFR_(13) TFR_(15) TFR_(26) TFR_(6)
    x0 += k1;  x1 += ks2 + 1u;
    TFR_(17) TFR_(29) TFR_(16) TFR_(24)
    x0 += ks2; x1 += k0 + 2u;
    TFR_(13) TFR_(15) TFR_(26) TFR_(6)
    x0 += k0;  x1 += k1 + 3u;
    TFR_(17) TFR_(29) TFR_(16) TFR_(24)
    x0 += k1;  x1 += ks2 + 4u;
    TFR_(13) TFR_(15) TFR_(26) TFR_(6)
    x0 += ks2; x1 += k0 + 5u;
#undef TFR_
    return x0 ^ x1;
}

// ---------------- XLA-matched math -------------------------------------------
__device__ __forceinline__ float tanh_x(float x) {
    float ax = fabsf(x);
    float xc = fminf(fmaxf(x, -7.90531110763549805f), 7.90531110763549805f);
    float x2 = __fmul_rn(xc, xc);
    float p = -2.76076847742355e-16f;
    p = fmaf(p, x2,  2.00018790482477e-13f);
    p = fmaf(p, x2, -8.60467152213735e-11f);
    p = fmaf(p, x2,  5.12229709037114e-08f);
    p = fmaf(p, x2,  1.48572235717979e-05f);
    p = fmaf(p, x2,  6.37261928875436e-04f);
    p = fmaf(p, x2,  4.89352455891786e-03f);
    float num = __fmul_rn(xc, p);
    float q = 1.19825839466702e-06f;
    q = fmaf(q, x2, 1.18534705686654e-04f);
    q = fmaf(q, x2, 2.26843463243900e-03f);
    q = fmaf(q, x2, 4.89352518554385e-03f);
    return (ax < 0.0004f) ? x : __fdiv_rn(num, q);
}

__device__ __forceinline__ float sig_x(float x) {
    return __fadd_rn(__fmul_rn(0.5f, tanh_x(__fmul_rn(0.5f, x))), 0.5f);
}

__device__ __forceinline__ float erfinv_x(float x) {
    float t = __fmul_rn(x, x);
    float w = -log1pf(-t);
    float p;
    if (w < 5.0f) {
        w = __fadd_rn(w, -2.5f);
        p = 2.81022636e-08f;
        p = __fadd_rn(__fmul_rn(p, w),  3.43273939e-07f);
        p = __fadd_rn(__fmul_rn(p, w), -3.5233877e-06f);
        p = __fadd_rn(__fmul_rn(p, w), -4.39150654e-06f);
        p = __fadd_rn(__fmul_rn(p, w),  0.00021858087f);
        p = __fadd_rn(__fmul_rn(p, w), -0.00125372503f);
        p = __fadd_rn(__fmul_rn(p, w), -0.00417768164f);
        p = __fadd_rn(__fmul_rn(p, w),  0.246640727f);
        p = __fadd_rn(__fmul_rn(p, w),  1.50140941f);
    } else {
        w = __fadd_rn(__fsqrt_rn(w), -3.0f);
        p = -0.000200214257f;
        p = __fadd_rn(__fmul_rn(p, w),  0.000100950558f);
        p = __fadd_rn(__fmul_rn(p, w),  0.00134934322f);
        p = __fadd_rn(__fmul_rn(p, w), -0.00367342844f);
        p = __fadd_rn(__fmul_rn(p, w),  0.00573950773f);
        p = __fadd_rn(__fmul_rn(p, w), -0.0076224613f);
        p = __fadd_rn(__fmul_rn(p, w),  0.00943887047f);
        p = __fadd_rn(__fmul_rn(p, w),  1.00167406f);
        p = __fadd_rn(__fmul_rn(p, w),  2.83297682f);
    }
    return __fmul_rn(p, x);
}

// ---------------- small kernels ----------------------------------------------
__global__ void init_state_kernel() {
    int e = blockIdx.x * 256 + threadIdx.x;
    if (e < R_*S_) { d_h1[e]=0.f; d_c1[e]=0.f; d_h2[e]=0.f; d_c2[e]=0.f; }
    if (e < R_)    { d_w[e] = 1.0f/1024.0f; }
}

// fragment interleave: global col C -> source gate-major col
__device__ __forceinline__ int src_col_map(int C) {
    int c = C & 127;
    int wn = c >> 6, r = c & 63;
    int u = r >> 3, j = (r >> 1) & 3, v = r & 1;
    int g = 2*(u >> 2) + v;
    int s = ((C & ~127) >> 2) + 16*wn + 4*(u & 3) + j;
    return g*128 + s;
}

__device__ __forceinline__ void split_h2(float e0, float e1, __half2* hi, __half2* lo) {
    __half h0 = __float2half_rn(e0);
    __half h1 = __float2half_rn(e1);
    __half l0 = __float2half_rn(__fadd_rn(e0, -__half2float(h0)));
    __half l1 = __float2half_rn(__fadd_rn(e1, -__half2float(h1)));
    *hi = __halves2half2(h0, h1);
    *lo = __halves2half2(l0, l1);
}

__global__ void build_wc_kernel(const float* __restrict__ W1, const float* __restrict__ U1,
                                const float* __restrict__ W2, const float* __restrict__ U2) {
    int i = blockIdx.x * 256 + threadIdx.x;   // over (KC_/2)*NG_
    if (i < (KC_/2)*NG_) {
        int k2 = i / NG_, C = i % NG_;
        int k = 2*k2;
        int src = src_col_map(C);
        float a0 = (k   < 128) ? W1[k*NG_ + src]     : U1[(k-128)*NG_ + src];
        float a1 = (k+1 < 128) ? W1[(k+1)*NG_ + src] : U1[(k+1-128)*NG_ + src];
        split_h2(a0, a1, &d_Wc1h[i], &d_Wc1l[i]);
        float b0 = (k   < 128) ? W2[k*NG_ + src]     : U2[(k-128)*NG_ + src];
        float b1 = (k+1 < 128) ? W2[(k+1)*NG_ + src] : U2[(k+1-128)*NG_ + src];
        split_h2(b0, b1, &d_Wc2h[i], &d_Wc2l[i]);
    }
}

// fused: categorical resample (warp 0) + state gather + noise; blocks >= R_ do obsprep
__global__ void __launch_bounds__(128) gather_kernel(const float* __restrict__ obs,
                                                     const float* __restrict__ W1,
                                                     const float* __restrict__ Wm1,
                                                     uint32_t a0, uint32_t a1,
                                                     uint32_t n0, uint32_t n1,
                                                     int t, int doRes) {
    int r = blockIdx.x;
    int tid = threadIdx.x;

    if (r >= R_) {   // obsprep role
        int b = r - R_;
        __shared__ float ob[O_];
        if (tid < O_) ob[tid] = obs[((size_t)b*T_ + t)*O_ + tid];
        __syncthreads();
        for (int c = tid; c < NG_; c += 128) {
            float acc = 0.f;
            #pragma unroll 8
            for (int o = 0; o < O_; o++)
                acc = fmaf(ob[o], W1[(size_t)(128 + o)*NG_ + c], acc);
            d_obsZ[b*NG_ + c] = acc;
        }
        for (int c = tid; c < H_; c += 128) {
            float a2 = 0.f;
            #pragma unroll 8
            for (int o = 0; o < O_; o++)
                a2 = fmaf(ob[o], Wm1[(size_t)o*H_ + c], a2);
            d_mObs[b*H_ + c] = a2;
        }
        return;
    }

    __shared__ int sidx;
    if (doRes) {
        if (tid < 32) {
            int lane = tid;
            const float* wb = d_w + (r & ~1023);
            uint32_t base = ((uint32_t)r) << 10;
            float best = -__int_as_float(0x7f800000);
            int bestj = 0;
            for (int it = 0; it < 32; it++) {
                int j = it*32 + lane;
                uint32_t bits = rb32(a0, a1, base + (uint32_t)j);
                float u01 = __uint_as_float((bits >> 9) | 0x3f800000u) - 1.0f;
                float u = fmaxf(TINY_, __fadd_rn(u01, TINY_));
                float l1 = logf(u);
                float g  = -logf(-l1);
                float v  = __fadd_rn(g, __ldg(&wb[j]));
                if (v > best) { best = v; bestj = j; }
            }
            for (int off = 16; off; off >>= 1) {
                float ov = __shfl_xor_sync(0xffffffffu, best, off);
                int   oj = __shfl_xor_sync(0xffffffffu, bestj, off);
                if (ov > best || (ov == best && oj < bestj)) { best = ov; bestj = oj; }
            }
            if (lane == 0) sidx = bestj;
        }
    } else if (tid == 0) {
        sidx = 0;
    }
    __syncthreads();

    int s = tid;
    int src = (r & ~1023) + sidx;
    uint32_t bits = rb32(n0, n1, (uint32_t)(r*S_ + s));
    float u01 = __uint_as_float((bits >> 9) | 0x3f800000u) - 1.0f;
    float u = fmaxf(LO_, __fadd_rn(__fmul_rn(u01, 2.0f), LO_));
    float nz = __fmul_rn((float)SQRT2_, erfinv_x(u));
    size_t r1 = (size_t)r * KC_;
    d_A1[r1 + s]        = nz;
    d_A1[r1 + 128 + s]  = d_h1[(size_t)src*S_ + s];
    d_c1g[(size_t)r*S_ + s] = d_c1[(size_t)src*S_ + s];
    d_A2[(size_t)r*KC_ + 128 + s] = d_h2[(size_t)src*S_ + s];
    d_c2g[(size_t)r*S_ + s] = d_c2[(size_t)src*S_ + s];
}

// ---------------- 3xFP16 (m16n8k16) GEMM + fused LSTM epilogue ---------------
// Half the HMMA instructions of 3xTF32 k8; C fragment layout identical, so the
// gate-interleave and epilogue are unchanged.
#define BM_ 128
#define BN_ 128
#define CH_ 16
#define PADC_ 136

template<int LAYER>
__global__ void __launch_bounds__(256, 2) gemm_lstm_kernel(const float* __restrict__ bias,
                                                           float* __restrict__ out, int t) {
    __shared__ __half2 sAh[2][8][PADC_], sAl[2][8][PADC_];
    __shared__ __half2 sBh[2][8][PADC_], sBl[2][8][PADC_];

    const int K = KC_;
    const float*   __restrict__ A   = (LAYER == 1) ? d_A1 : d_A2;
    const __half2* __restrict__ Whi = (LAYER == 1) ? d_Wc1h : d_Wc2h;
    const __half2* __restrict__ Wlo = (LAYER == 1) ? d_Wc1l : d_Wc2l;
    const float*   __restrict__ Cg  = (LAYER == 1) ? d_c1g : d_c2g;

    int tid = threadIdx.x;
    int warp = tid >> 5, lane = tid & 31;
    int wm = warp >> 1, wn = warp & 1;
    int q = lane >> 2, j = lane & 3;
    int rowBase = blockIdx.y * BM_;
    int colBase = blockIdx.x * BN_;     // in half2 columns (logical gate cols)
    const int NT = K / CH_;             // 16

    int ldRow = tid & 127, ldKq = tid >> 7;   // A: 2 threads/row, each 8 k's
    int bKp = tid >> 5, bC4 = (tid & 31) * 4; // B: kpair row, 4 half2 cols
    const float* aRow = A + (size_t)(rowBase + ldRow) * K;

    float acc[2][8][4];
    #pragma unroll
    for (int a = 0; a < 2; a++)
        #pragma unroll
        for (int u = 0; u < 8; u++)
            #pragma unroll
            for (int x = 0; x < 4; x++) acc[a][u][x] = 0.f;

    auto stage_a = [&](int buf, float4 v0, float4 v1) {
        float vals[8] = {v0.x, v0.y, v0.z, v0.w, v1.x, v1.y, v1.z, v1.w};
        #pragma unroll
        for (int p = 0; p < 4; p++) {
            __half2 hi, lo;
            split_h2(vals[2*p], vals[2*p+1], &hi, &lo);
            sAh[buf][ldKq*4 + p][ldRow] = hi;
            sAl[buf][ldKq*4 + p][ldRow] = lo;
        }
    };
    auto cp_b = [&](int kc, int buf) {
        const __half2* srcH = Whi + (size_t)(kc*8 + bKp)*NG_ + colBase + bC4;
        const __half2* srcL = Wlo + (size_t)(kc*8 + bKp)*NG_ + colBase + bC4;
        CP_ASYNC16(smem_u32(&sBh[buf][bKp][bC4]), srcH);
        CP_ASYNC16(smem_u32(&sBl[buf][bKp][bC4]), srcL);
        CP_COMMIT();
    };

    // prologue: chunk 0
    float4 av0 = *reinterpret_cast<const float4*>(aRow + ldKq*8);
    float4 av1 = *reinterpret_cast<const float4*>(aRow + ldKq*8 + 4);
    cp_b(0, 0);
    stage_a(0, av0, av1);
    CP_WAIT0();
    __syncthreads();

    for (int kt = 0; kt < NT; kt++) {
        int buf = kt & 1, nb = buf ^ 1;
        if (kt + 1 < NT) {
            int k0 = (kt + 1) * CH_;
            av0 = *reinterpret_cast<const float4*>(aRow + k0 + ldKq*8);
            av1 = *reinterpret_cast<const float4*>(aRow + k0 + ldKq*8 + 4);
            cp_b(kt + 1, nb);
        }

        uint32_t ah[2][4], al[2][4];
        #pragma unroll
        for (int mt = 0; mt < 2; mt++) {
            int g = wm*32 + mt*16 + q;
            ah[mt][0] = *(const uint32_t*)&sAh[buf][j  ][g];
            ah[mt][1] = *(const uint32_t*)&sAh[buf][j  ][g+8];
            ah[mt][2] = *(const uint32_t*)&sAh[buf][j+4][g];
            ah[mt][3] = *(const uint32_t*)&sAh[buf][j+4][g+8];
            al[mt][0] = *(const uint32_t*)&sAl[buf][j  ][g];
            al[mt][1] = *(const uint32_t*)&sAl[buf][j  ][g+8];
            al[mt][2] = *(const uint32_t*)&sAl[buf][j+4][g];
            al[mt][3] = *(const uint32_t*)&sAl[buf][j+4][g+8];
        }
        #pragma unroll
        for (int u = 0; u < 8; u++) {
            int c0 = wn*64 + u*8 + q;
            uint32_t bh[2], bl[2];
            bh[0] = *(const uint32_t*)&sBh[buf][j  ][c0];
            bh[1] = *(const uint32_t*)&sBh[buf][j+4][c0];
            bl[0] = *(const uint32_t*)&sBl[buf][j  ][c0];
            bl[1] = *(const uint32_t*)&sBl[buf][j+4][c0];
            #pragma unroll
            for (int mt = 0; mt < 2; mt++) {
                MMA_F16(acc[mt][u], ah[mt], bl);
                MMA_F16(acc[mt][u], al[mt], bh);
                MMA_F16(acc[mt][u], ah[mt], bh);
            }
        }

        if (kt + 1 < NT) {
            stage_a(nb, av0, av1);
            CP_WAIT0();
            __syncthreads();
        }
    }

    // ---------------- LSTM epilogue (unchanged) --------------------------
    int sBase = (colBase >> 2) + 16*wn;
    const float* oZ = (LAYER == 1) ? (d_obsZ + (size_t)(rowBase >> 10)*NG_) : nullptr;
    #pragma unroll
    for (int mt = 0; mt < 2; mt++) {
        #pragma unroll
        for (int half = 0; half < 2; half++) {
            int row = rowBase + wm*32 + mt*16 + q + half*8;
            #pragma unroll
            for (int ul = 0; ul < 4; ul++) {
                int s = sBase + 4*ul + j;
                float zi, zf, zg, zo;
                if (LAYER == 1) {
                    zi = __fadd_rn(__fadd_rn(acc[mt][ul  ][half*2+0], oZ[s]),       bias[s]);
                    zf = __fadd_rn(__fadd_rn(acc[mt][ul  ][half*2+1], oZ[128 + s]), bias[128 + s]);
                    zg = __fadd_rn(__fadd_rn(acc[mt][ul+4][half*2+0], oZ[256 + s]), bias[256 + s]);
                    zo = __fadd_rn(__fadd_rn(acc[mt][ul+4][half*2+1], oZ[384 + s]), bias[384 + s]);
                } else {
                    zi = __fadd_rn(acc[mt][ul  ][half*2+0], bias[s]);
                    zf = __fadd_rn(acc[mt][ul  ][half*2+1], bias[128 + s]);
                    zg = __fadd_rn(acc[mt][ul+4][half*2+0], bias[256 + s]);
                    zo = __fadd_rn(acc[mt][ul+4][half*2+1], bias[384 + s]);
                }
                float c  = Cg[(size_t)row*S_ + s];
                float cn = __fadd_rn(__fmul_rn(sig_x(zf), c), __fmul_rn(sig_x(zi), tanh_x(zg)));
                float hn = __fmul_rn(sig_x(zo), tanh_x(cn));
                if (LAYER == 1) {
                    d_h1[(size_t)row*S_ + s] = hn;
                    d_c1[(size_t)row*S_ + s] = cn;
                    d_A2[(size_t)row*KC_ + s] = hn;
                } else {
                    d_h2[(size_t)row*S_ + s] = hn;
                    d_c2[(size_t)row*S_ + s] = cn;
                    d_Am[(size_t)row*H_ + s] = hn;
                    int b = row >> 10, p = row & 1023;
                    out[(((size_t)b*T_ + t)*P_ + p)*129 + s] = hn;
                }
            }
        }
    }
}

// measurement MLP: w = relu(h2 @ Wm1[32:] + mObs + bm1) @ Wm2 + bm2
#define MEAS_ROWS 64
#define MEAS_SMEM ((H_*H_ + H_ + MEAS_ROWS*H_) * 4)
__global__ void __launch_bounds__(256) meas_kernel(const float* __restrict__ Wm1,
                                                   const float* __restrict__ bm1,
                                                   const float* __restrict__ Wm2,
                                                   const float* __restrict__ bm2,
                                                   float* __restrict__ out, int t) {
    extern __shared__ float sm[];
    float* sW  = sm;
    float* sW2 = sW + H_*H_;
    float* sR  = sW2 + H_;
    int tid = threadIdx.x;
    int rowBase = blockIdx.x * MEAS_ROWS;
    int bb = rowBase >> 10;
    for (int i = tid; i < H_*H_; i += 256) sW[i] = Wm1[O_*H_ + i];
    if (tid < H_) sW2[tid] = Wm2[tid];
    for (int i = tid; i < MEAS_ROWS*H_; i += 256) sR[i] = d_Am[(size_t)rowBase*H_ + i];
    __syncthreads();
    int warp = tid >> 5, lane = tid & 31;
    float b2v = bm2[0];
    const float* mOb = d_mObs + (size_t)bb*H_;
    for (int rl = warp; rl < MEAS_ROWS; rl += 8) {
        const float* x = sR + rl*H_;
        float d0 = 0.f, d1 = 0.f, d2 = 0.f, d3 = 0.f;
        #pragma unroll 4
        for (int k = 0; k < H_; k++) {
            float xv = x[k];
            float4 wv = *reinterpret_cast<const float4*>(&sW[k*H_ + lane*4]);
            d0 = fmaf(xv, wv.x, d0); d1 = fmaf(xv, wv.y, d1);
            d2 = fmaf(xv, wv.z, d2); d3 = fmaf(xv, wv.w, d3);
        }
        int c0 = lane*4;
        d0 = fmaxf(__fadd_rn(__fadd_rn(d0, mOb[c0+0]), bm1[c0+0]), 0.f);
        d1 = fmaxf(__fadd_rn(__fadd_rn(d1, mOb[c0+1]), bm1[c0+1]), 0.f);
        d2 = fmaxf(__fadd_rn(__fadd_rn(d2, mOb[c0+2]), bm1[c0+2]), 0.f);
        d3 = fmaxf(__fadd_rn(__fadd_rn(d3, mOb[c0+3]), bm1[c0+3]), 0.f);
        float acc = fmaf(d3, sW2[c0+3], fmaf(d2, sW2[c0+2], fmaf(d1, sW2[c0+1], __fmul_rn(d0, sW2[c0+0]))));
        for (int off = 16; off; off >>= 1) acc += __shfl_xor_sync(0xffffffffu, acc, off);
        if (lane == 0) {
            float wn = __fadd_rn(acc, b2v);
            int r = rowBase + rl;
            d_w[r] = wn;
            int b = r >> 10, p = r & 1023;
            out[(((size_t)b*T_ + t)*P_ + p)*129 + 128] = wn;
        }
    }
}

// ---------------- host side --------------------------------------------------
static inline uint32_t rotl32_h(uint32_t x, int r) { return (x << r) | (x >> (32 - r)); }
static void tf_host(uint32_t k0, uint32_t k1, uint32_t x0, uint32_t x1,
                    uint32_t* o0, uint32_t* o1) {
    uint32_t ks2 = k0 ^ k1 ^ 0x1BD11BDAu;
    x0 += k0; x1 += k1;
#define HR_(r) { x0 += x1; x1 = rotl32_h(x1, (r)); x1 ^= x0; }
    HR_(13) HR_(15) HR_(26) HR_(6)
    x0 += k1;  x1 += ks2 + 1u;
    HR_(17) HR_(29) HR_(16) HR_(24)
    x0 += ks2; x1 += k0 + 2u;
    HR_(13) HR_(15) HR_(26) HR_(6)
    x0 += k0;  x1 += k1 + 3u;
    HR_(17) HR_(29) HR_(16) HR_(24)
    x0 += k1;  x1 += ks2 + 4u;
    HR_(13) HR_(15) HR_(26) HR_(6)
    x0 += ks2; x1 += k0 + 5u;
#undef HR_
    *o0 = x0; *o1 = x1;
}

extern "C" void kernel_launch(void* const* d_in, const int* in_sizes, int n_in,
                              void* d_out, int out_size) {
    (void)in_sizes; (void)n_in; (void)out_size;
    const float* obs = (const float*)d_in[0];
    const float* W1  = (const float*)d_in[1];
    const float* U1  = (const float*)d_in[2];
    const float* b1  = (const float*)d_in[3];
    const float* W2  = (const float*)d_in[4];
    const float* U2  = (const float*)d_in[5];
    const float* b2  = (const float*)d_in[6];
    const float* Wm1 = (const float*)d_in[7];
    const float* bm1 = (const float*)d_in[8];
    const float* Wm2 = (const float*)d_in[9];
    const float* bm2 = (const float*)d_in[10];
    float* out = (float*)d_out;

    cudaFuncSetAttribute(meas_kernel, cudaFuncAttributeMaxDynamicSharedMemorySize, MEAS_SMEM);

    init_state_kernel<<<(R_*S_ + 255)/256, 256>>>();
    build_wc_kernel<<<((KC_/2)*NG_ + 255)/256, 256>>>(W1, U1, W2, U2);

    uint32_t root0 = 0u, root1 = 42u;
    for (int t = 0; t < T_; t++) {
        uint32_t kt0, kt1, a0, a1, n0, n1;
        tf_host(root0, root1, 0u, (uint32_t)t, &kt0, &kt1);
        tf_host(kt0, kt1, 0u, 0u, &a0, &a1);
        tf_host(kt0, kt1, 0u, 1u, &n0, &n1);

        // blocks [0,R_) resample+gather; blocks [R_, R_+B_) do the obs hoist
        gather_kernel<<<R_ + B_, 128>>>(obs, W1, Wm1, a0, a1, n0, n1, t, t > 0 ? 1 : 0);
        gemm_lstm_kernel<1><<<dim3(NG_/BN_, R_/BM_), 256>>>(b1, nullptr, t);
        gemm_lstm_kernel<2><<<dim3(NG_/BN_, R_/BM_), 256>>>(b2, out, t);
        meas_kernel<<<R_/MEAS_ROWS, 256, MEAS_SMEM>>>(Wm1, bm1, Wm2, bm2, out, t);
    }
}